// round 9
// baseline (speedup 1.0000x reference)
#include <cuda_runtime.h>
#include <stdint.h>
#include <math.h>

#define T_ROWS 65536
#define CD 128
#define HD 64
#define KSH 512
#define KCO 16
#define RPB 32                 // rows per block
#define NBLK (T_ROWS / RPB)    // 2048

#define LOSS_OFF 8388608ul
#define PS_OFF   8388609ul
#define PC_OFF   8388610ul
#define IDX_OFF  8388611ul
#define US_OFF   8454147ul
#define UC_OFF   8454659ul

#define XP 68                   // padded row stride (floats), odd # of float4
#define GAP 2.5e-4f             // screening margin >> cheap-gumbel error (~4.5e-5)

__device__ int    g_usage_s[KSH];
__device__ int    g_usage_c[KCO];
__device__ int    g_vcount;
__device__ int    g_ticket;
__device__ double g_loss_part[NBLK];

// ---------------- compile-time threefry for the two split keys ----------------
constexpr uint32_t rotl_c(uint32_t x, int d) { return (x << d) | (x >> (32 - d)); }
constexpr uint64_t tf_c(uint32_t k0, uint32_t k1, uint32_t x0, uint32_t x1) {
    uint32_t k2 = k0 ^ k1 ^ 0x1BD11BDAu;
    const int ra[4] = {13, 15, 26, 6};
    const int rb[4] = {17, 29, 16, 24};
    x0 += k0; x1 += k1;
    for (int i = 0; i < 4; i++) { x0 += x1; x1 = rotl_c(x1, ra[i]); x1 ^= x0; }
    x0 += k1; x1 += k2 + 1u;
    for (int i = 0; i < 4; i++) { x0 += x1; x1 = rotl_c(x1, rb[i]); x1 ^= x0; }
    x0 += k2; x1 += k0 + 2u;
    for (int i = 0; i < 4; i++) { x0 += x1; x1 = rotl_c(x1, ra[i]); x1 ^= x0; }
    x0 += k0; x1 += k1 + 3u;
    for (int i = 0; i < 4; i++) { x0 += x1; x1 = rotl_c(x1, rb[i]); x1 ^= x0; }
    x0 += k1; x1 += k2 + 4u;
    for (int i = 0; i < 4; i++) { x0 += x1; x1 = rotl_c(x1, ra[i]); x1 ^= x0; }
    x0 += k2; x1 += k0 + 5u;
    return ((uint64_t)x0 << 32) | x1;
}
constexpr uint64_t KS_P = tf_c(0u, 42u, 0u, 0u);
constexpr uint64_t KC_P = tf_c(0u, 42u, 0u, 1u);
constexpr uint32_t KS0v = (uint32_t)(KS_P >> 32), KS1v = (uint32_t)KS_P;
constexpr uint32_t KC0v = (uint32_t)(KC_P >> 32), KC1v = (uint32_t)KC_P;

// ---------------- packed f32x2 FMA (FFMA2 — PTX-only) ----------------
__device__ __forceinline__ unsigned long long ffma2(unsigned long long a,
                                                    unsigned long long b,
                                                    unsigned long long c) {
    unsigned long long d;
    asm("fma.rn.f32x2 %0, %1, %2, %3;" : "=l"(d) : "l"(a), "l"(b), "l"(c));
    return d;
}
__device__ __forceinline__ float fold2(unsigned long long a) {
    float2 p = *(float2*)&a;
    return __fadd_rn(p.x, p.y);
}

// ---------------- runtime threefry (keys are immediates) ----------------
__device__ __forceinline__ uint32_t rotl32(uint32_t x, int d) {
    return (x << d) | (x >> (32 - d));
}
__device__ __forceinline__ void tf_r(uint32_t& x0, uint32_t& x1, int r) {
    x0 += x1; x1 = rotl32(x1, r); x1 ^= x0;
}
__device__ __forceinline__ uint2 threefry2x32(uint32_t k0, uint32_t k1,
                                              uint32_t x0, uint32_t x1) {
    uint32_t k2 = k0 ^ k1 ^ 0x1BD11BDAu;
    x0 += k0; x1 += k1;
    tf_r(x0,x1,13); tf_r(x0,x1,15); tf_r(x0,x1,26); tf_r(x0,x1,6);
    x0 += k1; x1 += k2 + 1u;
    tf_r(x0,x1,17); tf_r(x0,x1,29); tf_r(x0,x1,16); tf_r(x0,x1,24);
    x0 += k2; x1 += k0 + 2u;
    tf_r(x0,x1,13); tf_r(x0,x1,15); tf_r(x0,x1,26); tf_r(x0,x1,6);
    x0 += k0; x1 += k1 + 3u;
    tf_r(x0,x1,17); tf_r(x0,x1,29); tf_r(x0,x1,16); tf_r(x0,x1,24);
    x0 += k1; x1 += k2 + 4u;
    tf_r(x0,x1,13); tf_r(x0,x1,15); tf_r(x0,x1,26); tf_r(x0,x1,6);
    x0 += k2; x1 += k0 + 5u;
    return make_uint2(x0, x1);
}

__device__ __forceinline__ float uniform_at(uint32_t k0, uint32_t k1, uint32_t idx) {
    uint2 r = threefry2x32(k0, k1, 0u, idx);
    uint32_t bits = r.x ^ r.y;
    const float TINY = 1.17549435e-38f;
    float f = __uint_as_float(0x3F800000u | (bits >> 9)) - 1.0f;
    return fmaxf(TINY, __fadd_rn(f, TINY));
}

__device__ __forceinline__ float gumbel_exact(uint32_t k0, uint32_t k1, uint32_t idx) {
    float u = uniform_at(k0, k1, idx);
    return -logf(-logf(u));
}

// cheap gumbel: |err| <= ~4.5e-5, branchless
__device__ __forceinline__ float gumbel_cheap(uint32_t k0, uint32_t k1, uint32_t idx) {
    float u = uniform_at(k0, k1, idx);
    float inner_m = -0.69314718056f * __log2f(u);
    float s = 1.0f - u;
    float inner_s = s * fmaf(s, fmaf(s, 0.33333333f, 0.5f), 1.0f);
    float inner = (u > 0.99609375f) ? inner_s : inner_m;
    return -0.69314718056f * __log2f(inner);
}

// ---------------- the single fused kernel ----------------
__global__ __launch_bounds__(256, 3) void k_main(const float* __restrict__ x,
                                                 const float* __restrict__ ws,
                                                 const float* __restrict__ wc,
                                                 float* __restrict__ out) {
    extern __shared__ __align__(16) char smem_raw[];
    float* sXs = (float*)smem_raw;            // 32*68
    float* sXc = sXs + RPB * XP;              // 32*68
    float* sW  = sXc + RPB * XP;              // 128*68
    float* sWc = sW  + 128 * XP;              // 16*68
    float* sWW = sWc + 16 * XP;               // 128
    float* sWWc = sWW + 128;                  // 16
    float* sXN = sWWc + 16;                   // 32
    float* sCN = sXN + RPB;                   // 32
    int*   sBG = (int*)(sCN + RPB);           // 32
    int*   sSI = sBG + RPB;                   // 32
    int*   sCI = sSI + RPB;                   // 32
    float* sLossW = (float*)(sCI + RPB);      // 8
    int*   sVC = (int*)(sLossW + 8);          // 1
    int*   sFG = sVC + 1;                     // 1

    __shared__ double sdd[256];
    __shared__ int isLast;

    int tid = threadIdx.x, lane = tid & 31, w = tid >> 5;
    int ci = tid & 15, ri = tid >> 4;         // ri in [0,16): row group
    int rowbase = blockIdx.x * RPB;

    if (tid == 0) { *sVC = 0; *sFG = 0; }

    // load X tile: 32 rows x 128 -> split halves into padded smem
    const float4* gx = (const float4*)(x + (size_t)rowbase * CD);
    #pragma unroll
    for (int i = tid; i < RPB * 32; i += 256) {
        float4 v = gx[i];
        int r = i >> 5, c4 = i & 31;
        if (c4 < 16) ((float4*)(sXs + r * XP))[c4] = v;
        else         ((float4*)(sXc + r * XP))[c4 - 16] = v;
    }
    // color codebook + norms (16 lanes per code row)
    {
        float4 v = ((const float4*)wc)[tid];
        ((float4*)(sWc + (tid >> 4) * XP))[tid & 15] = v;
        float pd = __fadd_rn(__fadd_rn(__fmul_rn(v.x, v.x), __fmul_rn(v.y, v.y)),
                             __fadd_rn(__fmul_rn(v.z, v.z), __fmul_rn(v.w, v.w)));
        #pragma unroll
        for (int o = 8; o > 0; o >>= 1)
            pd = __fadd_rn(pd, __shfl_xor_sync(0xffffffffu, pd, o));
        if ((tid & 15) == 0) sWWc[tid >> 4] = pd;
    }
    __syncthreads();

    // per-row bg + half-norms: warp w -> rows w*4..+3, 8 lanes per row
    {
        int r = w * 4 + (lane >> 3);
        int part = lane & 7;
        float sa = 0.f, ss = 0.f, sc = 0.f;
        #pragma unroll
        for (int j = 0; j < 8; j++) {
            float a = sXs[r * XP + part * 8 + j];
            float b = sXc[r * XP + part * 8 + j];
            sa += fabsf(a) + fabsf(b);
            ss = __fmaf_rn(a, a, ss);
            sc = __fmaf_rn(b, b, sc);
        }
        #pragma unroll
        for (int o = 1; o < 8; o <<= 1) {
            sa += __shfl_xor_sync(0xffffffffu, sa, o);
            ss += __shfl_xor_sync(0xffffffffu, ss, o);
            sc += __shfl_xor_sync(0xffffffffu, sc, o);
        }
        if (part == 0) {
            int b = (sa < 1e-6f);
            sBG[r] = b; sXN[r] = ss; sCN[r] = sc;
            if (!b) *sFG = 1;
        }
    }
    __syncthreads();
    int anyfg = *sFG;

    // finalist-pair screening state: top-2 value/code/logit, 2 rows per thread
    float v1[2], v2[2], lg1[2], lg2v[2];
    int   c1[2], c2[2];
    #pragma unroll
    for (int q = 0; q < 2; q++) {
        v1[q] = -INFINITY; v2[q] = -INFINITY;
        c1[q] = 0; c2[q] = 0; lg1[q] = 0.f; lg2v[q] = 0.f;
    }

#define EVAL_CAND(q_, lg_, code_)                                             \
    {                                                                         \
        float g_ = gumbel_cheap(KS0v, KS1v, rowoff + (uint32_t)(code_));      \
        float v_ = __fadd_rn(lg_, g_);                                        \
        if (v_ > v1[q_]) {                                                    \
            v2[q_] = v1[q_]; c2[q_] = c1[q_]; lg2v[q_] = lg1[q_];             \
            v1[q_] = v_; c1[q_] = (code_); lg1[q_] = (lg_);                   \
        } else if (v_ > v2[q_]) {                                             \
            v2[q_] = v_; c2[q_] = (code_); lg2v[q_] = (lg_);                  \
        }                                                                     \
    }

    if (anyfg) {
        for (int tile = 0; tile < 4; ++tile) {
            // load W tile + code norms
            const float4* gw = (const float4*)(ws + (size_t)tile * 128 * HD);
            #pragma unroll
            for (int i = tid; i < 128 * 16; i += 256) {
                float4 v = gw[i];
                ((float4*)(sW + (i >> 4) * XP))[i & 15] = v;
                float pd = __fadd_rn(__fadd_rn(__fmul_rn(v.x, v.x), __fmul_rn(v.y, v.y)),
                                     __fadd_rn(__fmul_rn(v.z, v.z), __fmul_rn(v.w, v.w)));
                #pragma unroll
                for (int o = 8; o > 0; o >>= 1)
                    pd = __fadd_rn(pd, __shfl_xor_sync(0xffffffffu, pd, o));
                if ((tid & 15) == 0) sWW[i >> 4] = pd;
            }
            __syncthreads();

            unsigned long long acc[2][8];
            #pragma unroll
            for (int q = 0; q < 2; q++)
                #pragma unroll
                for (int m = 0; m < 8; m++) acc[q][m] = 0ull;

            #pragma unroll
            for (int k4 = 0; k4 < 16; k4++) {
                ulonglong2 xv[2];
                #pragma unroll
                for (int q = 0; q < 2; q++)
                    xv[q] = ((const ulonglong2*)(sXs + (16 * q + ri) * XP))[k4];
                #pragma unroll
                for (int m = 0; m < 8; m++) {
                    ulonglong2 wv = ((const ulonglong2*)(sW + (ci + 16 * m) * XP))[k4];
                    #pragma unroll
                    for (int q = 0; q < 2; q++) {
                        acc[q][m] = ffma2(xv[q].x, wv.x, acc[q][m]);
                        acc[q][m] = ffma2(xv[q].y, wv.y, acc[q][m]);
                    }
                }
            }

            int cbase = tile * 128 + ci;
            #pragma unroll
            for (int q = 0; q < 2; q++) {
                int r = 16 * q + ri;
                uint32_t rowoff = (uint32_t)(rowbase + r) << 9;
                if (tile > 0) {
                    float lg = __fmaf_rn(2.f, fold2(acc[q][0]), -sWW[ci]);
                    EVAL_CAND(q, lg, cbase)       // codes 0..15 structurally skipped for fg
                }
                #pragma unroll
                for (int m = 1; m < 8; m++) {
                    float lg = __fmaf_rn(2.f, fold2(acc[q][m]), -sWW[ci + 16 * m]);
                    EVAL_CAND(q, lg, cbase + 16 * m)
                }
            }
            __syncthreads();
        }
    } else {
        // pure-bg block: only codes 0..15; x == 0 so logit = -ww
        {
            float4 v = ((const float4*)ws)[tid];   // first 16 code rows
            float pd = __fadd_rn(__fadd_rn(__fmul_rn(v.x, v.x), __fmul_rn(v.y, v.y)),
                                 __fadd_rn(__fmul_rn(v.z, v.z), __fmul_rn(v.w, v.w)));
            #pragma unroll
            for (int o = 8; o > 0; o >>= 1)
                pd = __fadd_rn(pd, __shfl_xor_sync(0xffffffffu, pd, o));
            if ((tid & 15) == 0) sWW[tid >> 4] = pd;
        }
        __syncthreads();
        #pragma unroll
        for (int q = 0; q < 2; q++) {
            int r = 16 * q + ri;
            uint32_t rowoff = (uint32_t)(rowbase + r) << 9;
            float lg = -sWW[ci];
            EVAL_CAND(q, lg, ci)
        }
    }

    // ---- color: exact path, 16 codes ----
    float cbest[2]; int cbidx[2];
    #pragma unroll
    for (int q = 0; q < 2; q++) {
        int r = 16 * q + ri;
        unsigned long long a2 = 0ull;
        #pragma unroll
        for (int k4 = 0; k4 < 16; k4++) {
            ulonglong2 xv = ((const ulonglong2*)(sXc + r * XP))[k4];
            ulonglong2 wv = ((const ulonglong2*)(sWc + ci * XP))[k4];
            a2 = ffma2(xv.x, wv.x, a2);
            a2 = ffma2(xv.y, wv.y, a2);
        }
        float a = fold2(a2);
        float g = gumbel_exact(KC0v, KC1v, ((uint32_t)(rowbase + r) << 4) + (uint32_t)ci);
        float d = __fadd_rn(__fadd_rn(sCN[r], sWWc[ci]), -__fmul_rn(2.f, a));
        cbest[q] = __fadd_rn(-d, g);
        cbidx[q] = ci;
    }

    // ---- cross-lane top-2 merge over the 16 ci lanes ----
    #pragma unroll
    for (int o = 8; o > 0; o >>= 1) {
        #pragma unroll
        for (int q = 0; q < 2; q++) {
            float ov1 = __shfl_xor_sync(0xffffffffu, v1[q], o);
            int   oc1 = __shfl_xor_sync(0xffffffffu, c1[q], o);
            float ol1 = __shfl_xor_sync(0xffffffffu, lg1[q], o);
            float ov2 = __shfl_xor_sync(0xffffffffu, v2[q], o);
            int   oc2 = __shfl_xor_sync(0xffffffffu, c2[q], o);
            float ol2 = __shfl_xor_sync(0xffffffffu, lg2v[q], o);
            bool takeO = (ov1 > v1[q]) || (ov1 == v1[q] && oc1 < c1[q]);
            float nv1 = takeO ? ov1 : v1[q];
            int   nc1 = takeO ? oc1 : c1[q];
            float nl1 = takeO ? ol1 : lg1[q];
            float lv = takeO ? v1[q] : ov1;
            int   lc = takeO ? c1[q] : oc1;
            float ll = takeO ? lg1[q] : ol1;
            float nv2 = lv; int nc2 = lc; float nl2 = ll;
            if (v2[q] > nv2 || (v2[q] == nv2 && c2[q] < nc2)) { nv2 = v2[q]; nc2 = c2[q]; nl2 = lg2v[q]; }
            if (ov2  > nv2 || (ov2  == nv2 && oc2  < nc2)) { nv2 = ov2;  nc2 = oc2;  nl2 = ol2; }
            v1[q] = nv1; c1[q] = nc1; lg1[q] = nl1;
            v2[q] = nv2; c2[q] = nc2; lg2v[q] = nl2;
            float cv = __shfl_xor_sync(0xffffffffu, cbest[q], o);
            int   cb = __shfl_xor_sync(0xffffffffu, cbidx[q], o);
            if (cv > cbest[q] || (cv == cbest[q] && cb < cbidx[q])) { cbest[q] = cv; cbidx[q] = cb; }
        }
    }
    if ((lane & 15) == 0) {
        #pragma unroll
        for (int q = 0; q < 2; q++) {
            int r = 16 * q + ri;
            int widx;
            if (sBG[r] && anyfg) {
                // impossible with this data; sound 16-code exact fallback
                float best = -INFINITY; widx = 0;
                for (int c = 0; c < KCO; c++) {
                    const float* wr = ws + c * HD;
                    float ww = 0.f;
                    for (int j = 0; j < HD; j++) ww = __fmaf_rn(wr[j], wr[j], ww);
                    float g = gumbel_exact(KS0v, KS1v, ((uint32_t)(rowbase + r) << 9) + (uint32_t)c);
                    float v = __fadd_rn(-ww, g);
                    if (v > best) { best = v; widx = c; }
                }
            } else if (v1[q] - v2[q] > GAP) {
                widx = c1[q];                     // certain winner
            } else {
                // rare: exact gumbel tie-break between the two finalists (O(1))
                uint32_t rowoff = (uint32_t)(rowbase + r) << 9;
                float e1 = __fadd_rn(lg1[q], gumbel_exact(KS0v, KS1v, rowoff + (uint32_t)c1[q]));
                float e2 = __fadd_rn(lg2v[q], gumbel_exact(KS0v, KS1v, rowoff + (uint32_t)c2[q]));
                widx = (e2 > e1 || (e2 == e1 && c2[q] < c1[q])) ? c2[q] : c1[q];
            }
            sSI[r] = widx;
            sCI[r] = cbidx[q];
        }
    }
    __syncthreads();

    // ---- outputs: quantized rows, idx, usage, loss ----
    float eacc = 0.f; int vcnt = 0;
    for (int t = 0; t < 4; t++) {
        int r = w * 4 + t;
        int widx = sSI[r], cidx = sCI[r];
        size_t grow = (size_t)rowbase + r;
        float4 wv, xv;
        if (lane < 16) {
            wv = ((const float4*)(ws + widx * HD))[lane];
            xv = ((const float4*)(sXs + r * XP))[lane];
        } else {
            wv = ((const float4*)(wc + cidx * HD))[lane - 16];
            xv = ((const float4*)(sXc + r * XP))[lane - 16];
        }
        ((float4*)out)[grow * 32 + lane] = wv;
        float dx = wv.x - xv.x, dy = wv.y - xv.y, dz = wv.z - xv.z, dw = wv.w - xv.w;
        float e = dx * dx + dy * dy + dz * dz + dw * dw;
        #pragma unroll
        for (int o = 16; o > 0; o >>= 1)
            e += __shfl_xor_sync(0xffffffffu, e, o);
        if (lane == 0) {
            out[IDX_OFF + grow] = (float)widx;
            if (!sBG[r]) {
                atomicAdd(&g_usage_s[widx], 1);
                atomicAdd(&g_usage_c[cidx], 1);
                vcnt++;
                eacc += e;
            }
        }
    }
    if (lane == 0) {
        sLossW[w] = eacc;
        atomicAdd(sVC, vcnt);
    }
    __syncthreads();
    if (tid == 0) {
        double L = 0.0;
        #pragma unroll
        for (int i = 0; i < 8; i++) L += (double)sLossW[i];
        g_loss_part[blockIdx.x] = L;
        atomicAdd(&g_vcount, *sVC);
    }

    // ---- last block finalizes + resets accumulators (graph-replay safe) ----
    __threadfence();
    if (tid == 0) {
        int t = atomicAdd(&g_ticket, 1);
        isLast = (t == NBLK - 1);
    }
    __syncthreads();
    if (!isLast) return;
    __threadfence();

    double a = 0.0;
    for (int i = tid; i < NBLK; i += 256) a += g_loss_part[i];
    sdd[tid] = a; __syncthreads();
    for (int s = 128; s > 0; s >>= 1) { if (tid < s) sdd[tid] += sdd[tid + s]; __syncthreads(); }
    double vc = (double)g_vcount;
    if (tid == 0) out[LOSS_OFF] = (float)(1.25 * sdd[0] / (vc * 128.0));
    __syncthreads();

    double e = 0.0;
    for (int i = tid; i < KSH; i += 256) {
        double p = (double)g_usage_s[i] / vc;
        e += p * log(p + 1e-10);
        out[US_OFF + i] = (float)g_usage_s[i];
    }
    sdd[tid] = e; __syncthreads();
    for (int s = 128; s > 0; s >>= 1) { if (tid < s) sdd[tid] += sdd[tid + s]; __syncthreads(); }
    if (tid == 0) out[PS_OFF] = (float)exp(-sdd[0]);
    __syncthreads();

    double ec = 0.0;
    if (tid < KCO) {
        double p = (double)g_usage_c[tid] / vc;
        ec = p * log(p + 1e-10);
        out[UC_OFF + tid] = (float)g_usage_c[tid];
    }
    sdd[tid] = ec; __syncthreads();
    for (int s = 128; s > 0; s >>= 1) { if (tid < s) sdd[tid] += sdd[tid + s]; __syncthreads(); }
    if (tid == 0) out[PC_OFF] = (float)exp(-sdd[0]);
    __syncthreads();

    for (int i = tid; i < KSH; i += 256) g_usage_s[i] = 0;
    if (tid < KCO) g_usage_c[tid] = 0;
    if (tid == 0) { g_vcount = 0; g_ticket = 0; }
}

#define SMEM_BYTES ((RPB*XP*2 + 128*XP + 16*XP + 128 + 16 + RPB + RPB) * 4 \
                    + (RPB + RPB + RPB + 8 + 1 + 1) * 4 + 64)

extern "C" void kernel_launch(void* const* d_in, const int* in_sizes, int n_in,
                              void* d_out, int out_size) {
    const float* x  = (const float*)d_in[0];   // inputs [16,4096,128]
    const float* ws = (const float*)d_in[2];   // w_shape [512,64]
    const float* wc = (const float*)d_in[3];   // w_color [16,64]
    float* out = (float*)d_out;
    cudaFuncSetAttribute(k_main, cudaFuncAttributeMaxDynamicSharedMemorySize, SMEM_BYTES);
    k_main<<<NBLK, 256, SMEM_BYTES>>>(x, ws, wc, out);
}

// round 10
// speedup vs baseline: 1.0353x; 1.0353x over previous
#include <cuda_runtime.h>
#include <stdint.h>
#include <math.h>

#define T_ROWS 65536
#define CD 128
#define HD 64
#define KSH 512
#define KCO 16
#define RPB 32                 // rows per block
#define NBLK (T_ROWS / RPB)    // 2048

#define LOSS_OFF 8388608ul
#define PS_OFF   8388609ul
#define PC_OFF   8388610ul
#define IDX_OFF  8388611ul
#define US_OFF   8454147ul
#define UC_OFF   8454659ul

#define XP 68                   // padded row stride (floats), odd # of float4
#define GAP 2.5e-4f             // screening margin >> cheap-gumbel error (~4.5e-5)

__device__ int    g_usage_s[KSH];
__device__ int    g_usage_c[KCO];
__device__ int    g_vcount;
__device__ int    g_ticket;
__device__ double g_loss_part[NBLK];

// ---------------- compile-time threefry for the two split keys ----------------
constexpr uint32_t rotl_c(uint32_t x, int d) { return (x << d) | (x >> (32 - d)); }
constexpr uint64_t tf_c(uint32_t k0, uint32_t k1, uint32_t x0, uint32_t x1) {
    uint32_t k2 = k0 ^ k1 ^ 0x1BD11BDAu;
    const int ra[4] = {13, 15, 26, 6};
    const int rb[4] = {17, 29, 16, 24};
    x0 += k0; x1 += k1;
    for (int i = 0; i < 4; i++) { x0 += x1; x1 = rotl_c(x1, ra[i]); x1 ^= x0; }
    x0 += k1; x1 += k2 + 1u;
    for (int i = 0; i < 4; i++) { x0 += x1; x1 = rotl_c(x1, rb[i]); x1 ^= x0; }
    x0 += k2; x1 += k0 + 2u;
    for (int i = 0; i < 4; i++) { x0 += x1; x1 = rotl_c(x1, ra[i]); x1 ^= x0; }
    x0 += k0; x1 += k1 + 3u;
    for (int i = 0; i < 4; i++) { x0 += x1; x1 = rotl_c(x1, rb[i]); x1 ^= x0; }
    x0 += k1; x1 += k2 + 4u;
    for (int i = 0; i < 4; i++) { x0 += x1; x1 = rotl_c(x1, ra[i]); x1 ^= x0; }
    x0 += k2; x1 += k0 + 5u;
    return ((uint64_t)x0 << 32) | x1;
}
constexpr uint64_t KS_P = tf_c(0u, 42u, 0u, 0u);
constexpr uint64_t KC_P = tf_c(0u, 42u, 0u, 1u);
constexpr uint32_t KS0v = (uint32_t)(KS_P >> 32), KS1v = (uint32_t)KS_P;
constexpr uint32_t KC0v = (uint32_t)(KC_P >> 32), KC1v = (uint32_t)KC_P;

// ---------------- packed f32x2 FMA (FFMA2 — PTX-only) ----------------
__device__ __forceinline__ unsigned long long ffma2(unsigned long long a,
                                                    unsigned long long b,
                                                    unsigned long long c) {
    unsigned long long d;
    asm("fma.rn.f32x2 %0, %1, %2, %3;" : "=l"(d) : "l"(a), "l"(b), "l"(c));
    return d;
}
__device__ __forceinline__ float fold2(unsigned long long a) {
    float2 p = *(float2*)&a;
    return __fadd_rn(p.x, p.y);
}

// ---------------- runtime threefry (keys are immediates) ----------------
__device__ __forceinline__ uint32_t rotl32(uint32_t x, int d) {
    return (x << d) | (x >> (32 - d));
}
__device__ __forceinline__ void tf_r(uint32_t& x0, uint32_t& x1, int r) {
    x0 += x1; x1 = rotl32(x1, r); x1 ^= x0;
}
__device__ __forceinline__ uint2 threefry2x32(uint32_t k0, uint32_t k1,
                                              uint32_t x0, uint32_t x1) {
    uint32_t k2 = k0 ^ k1 ^ 0x1BD11BDAu;
    x0 += k0; x1 += k1;
    tf_r(x0,x1,13); tf_r(x0,x1,15); tf_r(x0,x1,26); tf_r(x0,x1,6);
    x0 += k1; x1 += k2 + 1u;
    tf_r(x0,x1,17); tf_r(x0,x1,29); tf_r(x0,x1,16); tf_r(x0,x1,24);
    x0 += k2; x1 += k0 + 2u;
    tf_r(x0,x1,13); tf_r(x0,x1,15); tf_r(x0,x1,26); tf_r(x0,x1,6);
    x0 += k0; x1 += k1 + 3u;
    tf_r(x0,x1,17); tf_r(x0,x1,29); tf_r(x0,x1,16); tf_r(x0,x1,24);
    x0 += k1; x1 += k2 + 4u;
    tf_r(x0,x1,13); tf_r(x0,x1,15); tf_r(x0,x1,26); tf_r(x0,x1,6);
    x0 += k2; x1 += k0 + 5u;
    return make_uint2(x0, x1);
}

__device__ __forceinline__ float uniform_at(uint32_t k0, uint32_t k1, uint32_t idx) {
    uint2 r = threefry2x32(k0, k1, 0u, idx);
    uint32_t bits = r.x ^ r.y;
    const float TINY = 1.17549435e-38f;
    float f = __uint_as_float(0x3F800000u | (bits >> 9)) - 1.0f;
    return fmaxf(TINY, __fadd_rn(f, TINY));
}

__device__ __forceinline__ float gumbel_exact(uint32_t k0, uint32_t k1, uint32_t idx) {
    float u = uniform_at(k0, k1, idx);
    return -logf(-logf(u));
}

// cheap gumbel: |err| <= ~4.5e-5, branchless
__device__ __forceinline__ float gumbel_cheap(uint32_t k0, uint32_t k1, uint32_t idx) {
    float u = uniform_at(k0, k1, idx);
    float inner_m = -0.69314718056f * __log2f(u);
    float s = 1.0f - u;
    float inner_s = s * fmaf(s, fmaf(s, 0.33333333f, 0.5f), 1.0f);
    float inner = (u > 0.99609375f) ? inner_s : inner_m;
    return -0.69314718056f * __log2f(inner);
}

// ---------------- the single fused kernel ----------------
__global__ __launch_bounds__(256, 3) void k_main(const float* __restrict__ x,
                                                 const float* __restrict__ ws,
                                                 const float* __restrict__ wc,
                                                 float* __restrict__ out) {
    extern __shared__ __align__(16) char smem_raw[];
    float* sXs = (float*)smem_raw;            // 32*68
    float* sXc = sXs + RPB * XP;              // 32*68
    float* sW  = sXc + RPB * XP;              // 128*68
    float* sWc = sW  + 128 * XP;              // 16*68
    float* sWW = sWc + 16 * XP;               // 128
    float* sWWc = sWW + 128;                  // 16
    float* sXN = sWWc + 16;                   // 32
    float* sCN = sXN + RPB;                   // 32
    int*   sBG = (int*)(sCN + RPB);           // 32
    int*   sSI = sBG + RPB;                   // 32
    int*   sCI = sSI + RPB;                   // 32
    float* sLossW = (float*)(sCI + RPB);      // 8
    int*   sVC = (int*)(sLossW + 8);          // 1
    int*   sFG = sVC + 1;                     // 1
    int*   sNU = sFG + 1;                     // 1  (count of uncertain rows)
    int*   sUR = sNU + 1;                     // 32 (uncertain row ids)
    float* sRV = (float*)(sUR + RPB);         // 8  (redo reduce staging)
    int*   sRC = (int*)(sRV + 8);             // 8

    __shared__ double sdd[256];
    __shared__ int isLast;

    int tid = threadIdx.x, lane = tid & 31, w = tid >> 5;
    int ci = tid & 15, ri = tid >> 4;         // ri in [0,16): row group
    int rowbase = blockIdx.x * RPB;

    if (tid == 0) { *sVC = 0; *sFG = 0; *sNU = 0; }

    // load X tile: 32 rows x 128 -> split halves into padded smem
    const float4* gx = (const float4*)(x + (size_t)rowbase * CD);
    #pragma unroll
    for (int i = tid; i < RPB * 32; i += 256) {
        float4 v = gx[i];
        int r = i >> 5, c4 = i & 31;
        if (c4 < 16) ((float4*)(sXs + r * XP))[c4] = v;
        else         ((float4*)(sXc + r * XP))[c4 - 16] = v;
    }
    // color codebook + norms (16 lanes per code row)
    {
        float4 v = ((const float4*)wc)[tid];
        ((float4*)(sWc + (tid >> 4) * XP))[tid & 15] = v;
        float pd = __fadd_rn(__fadd_rn(__fmul_rn(v.x, v.x), __fmul_rn(v.y, v.y)),
                             __fadd_rn(__fmul_rn(v.z, v.z), __fmul_rn(v.w, v.w)));
        #pragma unroll
        for (int o = 8; o > 0; o >>= 1)
            pd = __fadd_rn(pd, __shfl_xor_sync(0xffffffffu, pd, o));
        if ((tid & 15) == 0) sWWc[tid >> 4] = pd;
    }
    __syncthreads();

    // per-row bg + half-norms: warp w -> rows w*4..+3, 8 lanes per row
    {
        int r = w * 4 + (lane >> 3);
        int part = lane & 7;
        float sa = 0.f, ss = 0.f, sc = 0.f;
        #pragma unroll
        for (int j = 0; j < 8; j++) {
            float a = sXs[r * XP + part * 8 + j];
            float b = sXc[r * XP + part * 8 + j];
            sa += fabsf(a) + fabsf(b);
            ss = __fmaf_rn(a, a, ss);
            sc = __fmaf_rn(b, b, sc);
        }
        #pragma unroll
        for (int o = 1; o < 8; o <<= 1) {
            sa += __shfl_xor_sync(0xffffffffu, sa, o);
            ss += __shfl_xor_sync(0xffffffffu, ss, o);
            sc += __shfl_xor_sync(0xffffffffu, sc, o);
        }
        if (part == 0) {
            int b = (sa < 1e-6f);
            sBG[r] = b; sXN[r] = ss; sCN[r] = sc;
            if (!b) *sFG = 1;
        }
    }
    __syncthreads();
    int anyfg = *sFG;

    // slim top-2 screening: values + winning code only
    float v1[2], v2[2];
    int   c1[2];
    #pragma unroll
    for (int q = 0; q < 2; q++) { v1[q] = -INFINITY; v2[q] = -INFINITY; c1[q] = 0; }

#define EVAL_CAND(q_, lg_, code_)                                             \
    {                                                                         \
        float g_ = gumbel_cheap(KS0v, KS1v, rowoff + (uint32_t)(code_));      \
        float v_ = __fadd_rn(lg_, g_);                                        \
        v2[q_] = fmaxf(v2[q_], fminf(v_, v1[q_]));                            \
        if (v_ > v1[q_]) c1[q_] = (code_);                                    \
        v1[q_] = fmaxf(v1[q_], v_);                                           \
    }

    if (anyfg) {
        for (int tile = 0; tile < 4; ++tile) {
            // load W tile + code norms
            const float4* gw = (const float4*)(ws + (size_t)tile * 128 * HD);
            #pragma unroll
            for (int i = tid; i < 128 * 16; i += 256) {
                float4 v = gw[i];
                ((float4*)(sW + (i >> 4) * XP))[i & 15] = v;
                float pd = __fadd_rn(__fadd_rn(__fmul_rn(v.x, v.x), __fmul_rn(v.y, v.y)),
                                     __fadd_rn(__fmul_rn(v.z, v.z), __fmul_rn(v.w, v.w)));
                #pragma unroll
                for (int o = 8; o > 0; o >>= 1)
                    pd = __fadd_rn(pd, __shfl_xor_sync(0xffffffffu, pd, o));
                if ((tid & 15) == 0) sWW[i >> 4] = pd;
            }
            __syncthreads();

            unsigned long long acc[2][8];
            #pragma unroll
            for (int q = 0; q < 2; q++)
                #pragma unroll
                for (int m = 0; m < 8; m++) acc[q][m] = 0ull;

            #pragma unroll
            for (int k4 = 0; k4 < 16; k4++) {
                ulonglong2 xv[2];
                #pragma unroll
                for (int q = 0; q < 2; q++)
                    xv[q] = ((const ulonglong2*)(sXs + (16 * q + ri) * XP))[k4];
                #pragma unroll
                for (int m = 0; m < 8; m++) {
                    ulonglong2 wv = ((const ulonglong2*)(sW + (ci + 16 * m) * XP))[k4];
                    #pragma unroll
                    for (int q = 0; q < 2; q++) {
                        acc[q][m] = ffma2(xv[q].x, wv.x, acc[q][m]);
                        acc[q][m] = ffma2(xv[q].y, wv.y, acc[q][m]);
                    }
                }
            }

            int cbase = tile * 128 + ci;
            #pragma unroll
            for (int q = 0; q < 2; q++) {
                int r = 16 * q + ri;
                uint32_t rowoff = (uint32_t)(rowbase + r) << 9;
                if (tile > 0) {
                    float lg = __fmaf_rn(2.f, fold2(acc[q][0]), -sWW[ci]);
                    EVAL_CAND(q, lg, cbase)       // codes 0..15 structurally skipped for fg
                }
                #pragma unroll
                for (int m = 1; m < 8; m++) {
                    float lg = __fmaf_rn(2.f, fold2(acc[q][m]), -sWW[ci + 16 * m]);
                    EVAL_CAND(q, lg, cbase + 16 * m)
                }
            }
            __syncthreads();
        }
    } else {
        // pure-bg block: only codes 0..15; x == 0 so logit = -ww
        {
            float4 v = ((const float4*)ws)[tid];   // first 16 code rows
            float pd = __fadd_rn(__fadd_rn(__fmul_rn(v.x, v.x), __fmul_rn(v.y, v.y)),
                                 __fadd_rn(__fmul_rn(v.z, v.z), __fmul_rn(v.w, v.w)));
            #pragma unroll
            for (int o = 8; o > 0; o >>= 1)
                pd = __fadd_rn(pd, __shfl_xor_sync(0xffffffffu, pd, o));
            if ((tid & 15) == 0) sWW[tid >> 4] = pd;
        }
        __syncthreads();
        #pragma unroll
        for (int q = 0; q < 2; q++) {
            int r = 16 * q + ri;
            uint32_t rowoff = (uint32_t)(rowbase + r) << 9;
            float lg = -sWW[ci];
            EVAL_CAND(q, lg, ci)
        }
    }

    // ---- color: exact path, 16 codes ----
    float cbest[2]; int cbidx[2];
    #pragma unroll
    for (int q = 0; q < 2; q++) {
        int r = 16 * q + ri;
        unsigned long long a2 = 0ull;
        #pragma unroll
        for (int k4 = 0; k4 < 16; k4++) {
            ulonglong2 xv = ((const ulonglong2*)(sXc + r * XP))[k4];
            ulonglong2 wv = ((const ulonglong2*)(sWc + ci * XP))[k4];
            a2 = ffma2(xv.x, wv.x, a2);
            a2 = ffma2(xv.y, wv.y, a2);
        }
        float a = fold2(a2);
        float g = gumbel_exact(KC0v, KC1v, ((uint32_t)(rowbase + r) << 4) + (uint32_t)ci);
        float d = __fadd_rn(__fadd_rn(sCN[r], sWWc[ci]), -__fmul_rn(2.f, a));
        cbest[q] = __fadd_rn(-d, g);
        cbidx[q] = ci;
    }

    // ---- cross-lane merges over the 16 ci lanes ----
    #pragma unroll
    for (int o = 8; o > 0; o >>= 1) {
        #pragma unroll
        for (int q = 0; q < 2; q++) {
            float ov1 = __shfl_xor_sync(0xffffffffu, v1[q], o);
            int   oc1 = __shfl_xor_sync(0xffffffffu, c1[q], o);
            float ov2 = __shfl_xor_sync(0xffffffffu, v2[q], o);
            v2[q] = fmaxf(fmaxf(v2[q], ov2), fminf(v1[q], ov1));
            if (ov1 > v1[q]) c1[q] = oc1;
            v1[q] = fmaxf(v1[q], ov1);
            float cv = __shfl_xor_sync(0xffffffffu, cbest[q], o);
            int   cb = __shfl_xor_sync(0xffffffffu, cbidx[q], o);
            if (cv > cbest[q] || (cv == cbest[q] && cb < cbidx[q])) { cbest[q] = cv; cbidx[q] = cb; }
        }
    }
    // write certain rows; collect uncertain rows for cooperative exact redo
    if ((lane & 15) == 0) {
        #pragma unroll
        for (int q = 0; q < 2; q++) {
            int r = 16 * q + ri;
            bool unc = !(v1[q] - v2[q] > GAP) || (sBG[r] && anyfg);
            if (unc) {
                int p = atomicAdd(sNU, 1);
                sUR[p] = r;
            } else {
                sSI[r] = c1[q];
            }
            sCI[r] = cbidx[q];
        }
    }
    __syncthreads();

    // ---- block-cooperative exact redo of uncertain rows (rare) ----
    int nu = *sNU;
    for (int u = 0; u < nu; u++) {
        int r = sUR[u];
        int bg = sBG[r];
        int lo = bg ? 0 : KCO;
        int hi = bg ? KCO : KSH;
        const float* xrow = sXs + r * XP;
        float xs = sXN[r];
        uint32_t rowoff = (uint32_t)(rowbase + r) << 9;
        float bv = -INFINITY; int bc = 0x7fffffff;
        for (int c = lo + tid; c < hi; c += 256) {
            const float* wr = ws + c * HD;
            float dot = 0.f, ww = 0.f;
            #pragma unroll
            for (int j = 0; j < HD; j++) {
                float wv = wr[j];
                dot = __fmaf_rn(xrow[j], wv, dot);
                ww  = __fmaf_rn(wv, wv, ww);
            }
            float d = __fadd_rn(__fadd_rn(xs, ww), -__fmul_rn(2.f, dot));
            float g = gumbel_exact(KS0v, KS1v, rowoff + (uint32_t)c);
            float v = __fadd_rn(-d, g);
            if (v > bv || (v == bv && c < bc)) { bv = v; bc = c; }
        }
        #pragma unroll
        for (int o = 16; o > 0; o >>= 1) {
            float ov = __shfl_xor_sync(0xffffffffu, bv, o);
            int   oc = __shfl_xor_sync(0xffffffffu, bc, o);
            if (ov > bv || (ov == bv && oc < bc)) { bv = ov; bc = oc; }
        }
        if (lane == 0) { sRV[w] = bv; sRC[w] = bc; }
        __syncthreads();
        if (tid == 0) {
            float fv = sRV[0]; int fc = sRC[0];
            #pragma unroll
            for (int i = 1; i < 8; i++)
                if (sRV[i] > fv || (sRV[i] == fv && sRC[i] < fc)) { fv = sRV[i]; fc = sRC[i]; }
            sSI[r] = fc;
        }
        __syncthreads();
    }

    // ---- outputs: quantized rows, idx, usage, loss ----
    float eacc = 0.f; int vcnt = 0;
    for (int t = 0; t < 4; t++) {
        int r = w * 4 + t;
        int widx = sSI[r], cidx = sCI[r];
        size_t grow = (size_t)rowbase + r;
        float4 wv, xv;
        if (lane < 16) {
            wv = ((const float4*)(ws + widx * HD))[lane];
            xv = ((const float4*)(sXs + r * XP))[lane];
        } else {
            wv = ((const float4*)(wc + cidx * HD))[lane - 16];
            xv = ((const float4*)(sXc + r * XP))[lane - 16];
        }
        ((float4*)out)[grow * 32 + lane] = wv;
        float dx = wv.x - xv.x, dy = wv.y - xv.y, dz = wv.z - xv.z, dw = wv.w - xv.w;
        float e = dx * dx + dy * dy + dz * dz + dw * dw;
        #pragma unroll
        for (int o = 16; o > 0; o >>= 1)
            e += __shfl_xor_sync(0xffffffffu, e, o);
        if (lane == 0) {
            out[IDX_OFF + grow] = (float)widx;
            if (!sBG[r]) {
                atomicAdd(&g_usage_s[widx], 1);
                atomicAdd(&g_usage_c[cidx], 1);
                vcnt++;
                eacc += e;
            }
        }
    }
    if (lane == 0) {
        sLossW[w] = eacc;
        atomicAdd(sVC, vcnt);
    }
    __syncthreads();
    if (tid == 0) {
        double L = 0.0;
        #pragma unroll
        for (int i = 0; i < 8; i++) L += (double)sLossW[i];
        g_loss_part[blockIdx.x] = L;
        atomicAdd(&g_vcount, *sVC);
    }

    // ---- last block finalizes + resets accumulators (graph-replay safe) ----
    __threadfence();
    if (tid == 0) {
        int t = atomicAdd(&g_ticket, 1);
        isLast = (t == NBLK - 1);
    }
    __syncthreads();
    if (!isLast) return;
    __threadfence();

    double a = 0.0;
    for (int i = tid; i < NBLK; i += 256) a += g_loss_part[i];
    sdd[tid] = a; __syncthreads();
    for (int s = 128; s > 0; s >>= 1) { if (tid < s) sdd[tid] += sdd[tid + s]; __syncthreads(); }
    double vc = (double)g_vcount;
    if (tid == 0) out[LOSS_OFF] = (float)(1.25 * sdd[0] / (vc * 128.0));
    __syncthreads();

    double e = 0.0;
    for (int i = tid; i < KSH; i += 256) {
        double p = (double)g_usage_s[i] / vc;
        e += p * log(p + 1e-10);
        out[US_OFF + i] = (float)g_usage_s[i];
    }
    sdd[tid] = e; __syncthreads();
    for (int s = 128; s > 0; s >>= 1) { if (tid < s) sdd[tid] += sdd[tid + s]; __syncthreads(); }
    if (tid == 0) out[PS_OFF] = (float)exp(-sdd[0]);
    __syncthreads();

    double ec = 0.0;
    if (tid < KCO) {
        double p = (double)g_usage_c[tid] / vc;
        ec = p * log(p + 1e-10);
        out[UC_OFF + tid] = (float)g_usage_c[tid];
    }
    sdd[tid] = ec; __syncthreads();
    for (int s = 128; s > 0; s >>= 1) { if (tid < s) sdd[tid] += sdd[tid + s]; __syncthreads(); }
    if (tid == 0) out[PC_OFF] = (float)exp(-sdd[0]);
    __syncthreads();

    for (int i = tid; i < KSH; i += 256) g_usage_s[i] = 0;
    if (tid < KCO) g_usage_c[tid] = 0;
    if (tid == 0) { g_vcount = 0; g_ticket = 0; }
}

#define SMEM_BYTES ((RPB*XP*2 + 128*XP + 16*XP + 128 + 16 + RPB + RPB) * 4 \
                    + (RPB + RPB + RPB + 8 + 1 + 1) * 4 + (1 + RPB + 8 + 8) * 4 + 64)

extern "C" void kernel_launch(void* const* d_in, const int* in_sizes, int n_in,
                              void* d_out, int out_size) {
    const float* x  = (const float*)d_in[0];   // inputs [16,4096,128]
    const float* ws = (const float*)d_in[2];   // w_shape [512,64]
    const float* wc = (const float*)d_in[3];   // w_color [16,64]
    float* out = (float*)d_out;
    cudaFuncSetAttribute(k_main, cudaFuncAttributeMaxDynamicSharedMemorySize, SMEM_BYTES);
    k_main<<<NBLK, 256, SMEM_BYTES>>>(x, ws, wc, out);
}